// round 13
// baseline (speedup 1.0000x reference)
#include <cuda_runtime.h>
#include <cuda_bf16.h>

#define NPRI    8732
#define NCLS    21
#define NBATCH  8
#define NLANES  (NBATCH * NCLS)   // 168
#define PPITCH  8736
#define TOPK    200
#define MCAND   600
#define NGMAX   19
#define MPITCH  601
#define CAP     1024
#define CONF_TH 0.95f
#define NMS_TH  0.45f
#define HTHREADS 512
#define NWARPS  16

__device__ float              g_confT[NLANES][PPITCH];
__device__ unsigned long long g_key[NLANES][MCAND];
__device__ int2               g_meta[NLANES];     // {count, fp}

struct __align__(16) SmemB {
    unsigned long long key[MCAND];
    float4             box[MCAND];
    float              area[MCAND];
    float4             wbox[MCAND];
    float              warea[MCAND];
    unsigned           wmask[NGMAX * MPITCH];
    short              cidx[MCAND];
    unsigned           wfball[NGMAX];
    unsigned           flagb[NGMAX];
    int                wfoff[NGMAX + 1];
    int                ctoff[NGMAX + 1];
    unsigned           kwbits[NGMAX];
    int                nwf, ntot;
};

#define BSYNC() asm volatile("bar.sync %0, 512;" :: "r"(half + 1) : "memory")

static __device__ __forceinline__ unsigned long long shfl_xor_u64(unsigned long long v, int m) {
    unsigned lo = __shfl_xor_sync(0xFFFFFFFFu, (unsigned)v, m);
    unsigned hi = __shfl_xor_sync(0xFFFFFFFFu, (unsigned)(v >> 32), m);
    return ((unsigned long long)hi << 32) | lo;
}

// ============ K0: tiled transpose conf[B,P,C] -> confT[B*C][P] ============
__global__ void __launch_bounds__(672)
k0_transpose(const float* __restrict__ conf)
{
    __shared__ float s[672];
    const int tile = blockIdx.x;
    const int bb = tile / 273;
    const int p0 = (tile - bb * 273) * 32;
    const int tid = threadIdx.x;
    const int nv = min(32, NPRI - p0) * NCLS;
    if (tid < nv)
        s[tid] = __ldg(conf + ((size_t)bb * NPRI + p0) * NCLS + tid);
    __syncthreads();
    const int c = tid / 32, pl = tid % 32;
    if (p0 + pl < NPRI)
        g_confT[bb * NCLS + c][p0 + pl] = s[pl * NCLS + c];
}

// ============ KA: collect + sort (tiny smem -> high occupancy, tail hidden) ============
__global__ void __launch_bounds__(HTHREADS)
ka_sort()
{
    __shared__ unsigned long long key[CAP];
    __shared__ int s_count, s_fp;

    const int lane_id = blockIdx.x;
    const int c = lane_id % NCLS;
    const int tid = threadIdx.x, lane = tid & 31;
    const unsigned lanem_lt = (1u << lane) - 1u;
    if (c == 0) return;                            // KB zeros these lanes

    if (tid == 0) { s_count = 0; s_fp = 0x7FFFFFFF; }
    __syncthreads();

    // ---- collect passers (coalesced, 9-deep preload x2, warp-aggregated push) ----
    const float* confc = g_confT[lane_id];
    #pragma unroll
    for (int half2 = 0; half2 < 2; ++half2) {
        float sv[9];
        #pragma unroll
        for (int t = 0; t < 9; ++t) {
            int p = tid + (half2 * 9 + t) * HTHREADS;
            sv[t] = (p < NPRI) ? confc[p] : 0.0f;
        }
        #pragma unroll
        for (int t = 0; t < 9; ++t) {
            int p = tid + (half2 * 9 + t) * HTHREADS;
            bool pass = sv[t] > CONF_TH;
            unsigned m = __ballot_sync(0xFFFFFFFFu, pass);
            if (m) {
                int leader = __ffs(m) - 1, bp = 0;
                if (lane == leader) {
                    bp = atomicAdd(&s_count, __popc(m));
                    atomicMin(&s_fp, p);
                }
                bp = __shfl_sync(0xFFFFFFFFu, bp, leader);
                if (pass) {
                    int pos = bp + __popc(m & lanem_lt);
                    if (pos < CAP)
                        key[pos] = ((unsigned long long)__float_as_uint(sv[t]) << 32)
                                 | (unsigned)(0xFFFFFFFFu - (unsigned)p);
                }
            }
        }
    }
    __syncthreads();
    const int count = min(s_count, CAP);
    if (tid == 0) g_meta[lane_id] = make_int2(count, s_fp);
    if (count == 0) return;

    // ---- descending bitonic sort ----
    if (count <= 512) {
        unsigned long long v = (tid < count) ? key[tid] : 0ull;
        #pragma unroll
        for (int k = 2; k <= 32; k <<= 1) {
            #pragma unroll
            for (int j = k >> 1; j; j >>= 1) {
                unsigned long long o = shfl_xor_u64(v, j);
                bool takeMax = (((tid & k) == 0) == ((tid & j) == 0));
                bool gt = v > o;
                v = (takeMax == gt) ? v : o;
            }
        }
        key[tid] = v;
        #pragma unroll
        for (int k = 64; k <= 512; k <<= 1) {
            for (int j = k >> 1; j >= 32; j >>= 1) {
                __syncthreads();
                if ((tid & j) == 0) {
                    int l = tid ^ j;
                    unsigned long long a = key[tid], bb = key[l];
                    if (((tid & k) == 0) ? (a < bb) : (a > bb)) { key[tid] = bb; key[l] = a; }
                }
            }
            __syncthreads();
            v = key[tid];
            const bool up = ((tid & k) == 0);
            #pragma unroll
            for (int j = 16; j; j >>= 1) {
                unsigned long long o = shfl_xor_u64(v, j);
                bool takeMax = (up == ((tid & j) == 0));
                bool gt = v > o;
                v = (takeMax == gt) ? v : o;
            }
            key[tid] = v;
        }
        __syncthreads();
    } else {
        const int n2 = 1 << (32 - __clz(count - 1));
        for (int i = count + tid; i < n2; i += HTHREADS) key[i] = 0ull;
        for (int k = 2; k <= n2; k <<= 1) {
            for (int j = k >> 1; j > 0; j >>= 1) {
                __syncthreads();
                for (int i = tid; i < n2; i += HTHREADS) {
                    int l = i ^ j;
                    if (l > i) {
                        unsigned long long a = key[i], bb = key[l];
                        if (((i & k) == 0) ? (a < bb) : (a > bb)) { key[i] = bb; key[l] = a; }
                    }
                }
            }
        }
        __syncthreads();
    }

    const int M = min(count, MCAND);
    for (int t = tid; t < M; t += HTHREADS) g_key[lane_id][t] = key[t];
}

// ============ KB: gather + compact + mask + sweep + output (2 lanes/block) ============
__global__ void __launch_bounds__(1024)
kb_nms(const float* __restrict__ loc, float* __restrict__ out)
{
    extern __shared__ unsigned char raw[];
    const int half = threadIdx.x >> 9;
    SmemB& S = reinterpret_cast<SmemB*>(raw)[half];

    const int lane_id = blockIdx.x * 2 + half;
    const int b = lane_id / NCLS, c = lane_id % NCLS;
    float* outp = out + (size_t)lane_id * TOPK * 5;
    const int tid = threadIdx.x & (HTHREADS - 1);
    const int lane = tid & 31, warp = tid >> 5;
    const unsigned lanem_lt = (1u << lane) - 1u;

    if (c == 0) {
        for (int i = tid; i < TOPK * 5; i += HTHREADS) outp[i] = 0.0f;
        return;
    }
    const int2 meta = g_meta[lane_id];
    const int count = meta.x, fp = meta.y;
    if (count == 0) {
        for (int i = tid; i < TOPK * 5; i += HTHREADS) outp[i] = 0.0f;
        return;
    }
    const int M = min(count, MCAND);
    const int ngroups = (M + 31) >> 5;

    // ---- load sorted keys + gather boxes ----
    for (int t = tid; t < M; t += HTHREADS) S.key[t] = g_key[lane_id][t];
    BSYNC();
    for (int t = tid; t < M; t += HTHREADS) {
        int p = (int)(0xFFFFFFFFu - (unsigned)(S.key[t] & 0xFFFFFFFFu));
        float4 L = __ldg((const float4*)(loc + ((size_t)b * NPRI + p) * 4));
        S.box[t]  = L;
        S.area[t] = (L.z - L.x) * (L.w - L.y);
    }
    BSYNC();

    // ---- compaction of well-formed boxes (degenerates never interact) ----
    for (int cs = warp; cs < ngroups; cs += NWARPS) {
        int t = cs * 32 + lane;
        bool wf = false;
        if (t < M) { float4 B = S.box[t]; wf = (B.z > B.x) && (B.w > B.y); }
        unsigned m = __ballot_sync(0xFFFFFFFFu, wf);
        if (lane == 0) { S.wfball[cs] = m; S.wfoff[cs] = __popc(m); }
    }
    BSYNC();
    if (tid == 0) {
        int run = 0;
        for (int cs = 0; cs < ngroups; ++cs) { int cc = S.wfoff[cs]; S.wfoff[cs] = run; run += cc; }
        S.nwf = run;
    }
    BSYNC();
    const int nwf = S.nwf;
    for (int cs = warp; cs < ngroups; cs += NWARPS) {
        int t = cs * 32 + lane;
        if (t < M) {
            unsigned m = S.wfball[cs];
            bool wf = (m >> lane) & 1u;
            int pos = S.wfoff[cs] + __popc(m & lanem_lt);
            S.cidx[t] = wf ? (short)pos : (short)-1;
            if (wf) { S.wbox[pos] = S.box[t]; S.warea[pos] = S.area[t]; }
        }
    }
    BSYNC();

    const int ngw = (nwf + 31) >> 5;

    // ---- IoU mask on compact set ----
    {
        int tcnt = 0;
        for (int w = 0; w < ngw; ++w) {
            const int j0 = w * 32;
            const int jmax = min(32, nwf - j0);
            for (int g = 0; g <= w; ++g, ++tcnt) {
                if ((tcnt & (NWARPS - 1)) != warp) continue;
                const int i = g * 32 + lane;
                const bool rv = i < nwf;
                float4 bi = rv ? S.wbox[i] : make_float4(0, 0, 0, 0);
                float  ai = rv ? S.warea[i] : 0.0f;
                unsigned bits = 0, uncb = 0;
                #pragma unroll 8
                for (int t2 = 0; t2 < jmax; ++t2) {
                    float4 bj = S.wbox[j0 + t2];
                    float  aj = S.warea[j0 + t2];
                    float inter = fmaxf(fminf(bi.z, bj.z) - fmaxf(bi.x, bj.x), 0.0f)
                                * fmaxf(fminf(bi.w, bj.w) - fmaxf(bi.y, bj.y), 0.0f);
                    float un = ai + aj - inter;
                    float d  = fmaf(-NMS_TH, un, inter);
                    float mg = 2e-6f * (fabsf(inter) + fabsf(un));
                    bool sup = (un > 0.0f) ? (d > mg) : (d < -mg);
                    bool unc = !(fabsf(d) > mg) || (un == 0.0f);
                    if (sup) bits |= 1u << t2;
                    if (unc) uncb |= 1u << t2;
                }
                if (uncb) {
                    do {
                        int t2 = __ffs(uncb) - 1; uncb &= uncb - 1;
                        float4 bj = S.wbox[j0 + t2];
                        float  aj = S.warea[j0 + t2];
                        float inter = fmaxf(fminf(bi.z, bj.z) - fmaxf(bi.x, bj.x), 0.0f)
                                    * fmaxf(fminf(bi.w, bj.w) - fmaxf(bi.y, bj.y), 0.0f);
                        float un = ai + aj - inter;
                        if (__fdiv_rn(inter, un) > NMS_TH) bits |= 1u << t2;
                        else bits &= ~(1u << t2);
                    } while (uncb);
                }
                if (g == w) bits &= (0xFFFFFFFEu << lane);
                if (rv) S.wmask[w * MPITCH + i] = bits;
            }
        }
    }
    BSYNC();

    // ---- compact greedy sweep (warp 0 of this half) ----
    if (warp == 0 && nwf > 0) {
        unsigned acc = 0;
        for (int w = 0; w < ngw; ++w) {
            unsigned cur = __shfl_sync(0xFFFFFFFFu, acc, w);
            unsigned chunkkeep = 0;
            for (int sub = 0; sub < 4; ++sub) {
                const int ibase = w * 32 + sub * 8;
                if (ibase >= nwf) break;
                const int nv = min(8, nwf - ibase);
                const unsigned validm = (nv == 8) ? 0xFFu : ((1u << nv) - 1u);
                unsigned selfm[8], rowm[8], selfor = 0;
                #pragma unroll
                for (int t = 0; t < 8; ++t) {
                    bool vld = t < nv;
                    int i = ibase + t;
                    selfm[t] = vld ? S.wmask[w * MPITCH + i] : 0u;
                    rowm[t]  = (vld && lane >= w && lane < ngw)
                             ? S.wmask[lane * MPITCH + i] : 0u;
                    selfor |= selfm[t];
                }
                unsigned keepb;
                if (selfor == 0) {
                    keepb = validm & ~((cur >> (sub * 8)) & 0xFFu);
                    #pragma unroll
                    for (int t = 0; t < 8; ++t)
                        acc |= rowm[t] & (unsigned)(-(int)((keepb >> t) & 1u));
                } else {
                    keepb = 0;
                    #pragma unroll
                    for (int t = 0; t < 8; ++t) {
                        int kbit = sub * 8 + t;
                        if (((validm >> t) & 1u) && !((cur >> kbit) & 1u)) {
                            keepb |= 1u << t;
                            cur |= selfm[t];
                            acc |= rowm[t];
                        }
                    }
                }
                chunkkeep |= keepb << (sub * 8);
            }
            if (lane == 0) S.kwbits[w] = chunkkeep;
        }
    }
    BSYNC();

    // ---- flag scan + scatter output ----
    for (int cs = warp; cs < ngroups; cs += NWARPS) {
        int t = cs * 32 + lane;
        bool flag = false;
        if (t < M) {
            int ci = S.cidx[t];
            flag = (ci < 0) ? true : (((S.kwbits[ci >> 5] >> (ci & 31)) & 1u) != 0);
        }
        unsigned fb = __ballot_sync(0xFFFFFFFFu, flag);
        if (lane == 0) { S.flagb[cs] = fb; S.ctoff[cs] = __popc(fb); }
    }
    BSYNC();
    if (tid == 0) {
        int run = 0;
        for (int cs = 0; cs < ngroups; ++cs) { int cc = S.ctoff[cs]; S.ctoff[cs] = run; run += cc; }
        S.ntot = run;
    }
    BSYNC();
    const int n = min(S.ntot, TOPK);

    for (int cs = warp; cs < ngroups; cs += NWARPS) {
        int t = cs * 32 + lane;
        unsigned fb = S.flagb[cs];
        bool flag = ((fb >> lane) & 1u) && (t < M);
        int rank = S.ctoff[cs] + __popc(fb & lanem_lt);
        if (flag && rank < TOPK) {
            float sc = __uint_as_float((unsigned)(S.key[t] >> 32));
            float4 bb = S.box[t];
            float* o = outp + rank * 5;
            o[0] = sc; o[1] = bb.x; o[2] = bb.y; o[3] = bb.z; o[4] = bb.w;
        }
    }
    {
        float4 fb4 = __ldg((const float4*)(loc + ((size_t)b * NPRI + fp) * 4));
        for (int r = n + tid; r < TOPK; r += HTHREADS) {
            float* o = outp + r * 5;
            o[0] = 0.0f; o[1] = fb4.x; o[2] = fb4.y; o[3] = fb4.z; o[4] = fb4.w;
        }
    }
}

extern "C" void kernel_launch(void* const* d_in, const int* in_sizes, int n_in,
                              void* d_out, int out_size)
{
    const float* loc  = (const float*)d_in[0];   // [8, 8732, 4]
    const float* conf = (const float*)d_in[1];   // [8, 8732, 21]
    float* out = (float*)d_out;                  // [8, 21, 200, 5]

    static int configured = 0;
    if (!configured) {
        cudaFuncSetAttribute(kb_nms,
                             cudaFuncAttributeMaxDynamicSharedMemorySize,
                             (int)(2 * sizeof(SmemB)));
        configured = 1;
    }
    k0_transpose<<<NBATCH * 273, 672>>>(conf);
    ka_sort<<<NLANES, HTHREADS>>>();
    kb_nms<<<NLANES / 2, 1024, 2 * sizeof(SmemB)>>>(loc, out);
}

// round 14
// speedup vs baseline: 1.3514x; 1.3514x over previous
#include <cuda_runtime.h>
#include <cuda_bf16.h>

#define NPRI    8732
#define NCLS    21
#define NBATCH  8
#define NLANES  (NBATCH * NCLS)   // 168
#define PPITCH  8736
#define TOPK    200
#define MCAND   600
#define NGMAX   19
#define MPITCH  601
#define CAP     1024
#define CONF_TH 0.95f
#define NMS_TH  0.45f
#define NTHREADS 512
#define NWARPS  16
#define NBUCK   1664              // covers ((1.0f bits)-(0.95f bits))>>9 = 1638, padded
#define TP      128               // priors per transpose tile
#define NTILE   69                // ceil(8732/128)

__device__ float g_confT[NLANES][PPITCH];

struct __align__(16) Smem {
    unsigned long long key[CAP];
    float4             box[MCAND];
    float              area[MCAND];
    float4             wbox[MCAND];     // also reused as u64 scatter buffer in sort
    float              warea[MCAND];
    unsigned           wmask[NGMAX * MPITCH]; // also reused as hist/hoff/arr in sort
    short              cidx[MCAND];
    unsigned           wfball[NGMAX];
    unsigned           flagb[NGMAX];
    int                wfoff[NGMAX + 1];
    int                ctoff[NGMAX + 1];
    unsigned           kwbits[NGMAX];
    unsigned           wscan[NWARPS];
    int                count, fp, nwf, ntot;
};

// ============ K0: vectorized tiled transpose conf[B,P,C] -> confT[B*C][P] ============
__global__ void __launch_bounds__(256)
k0_transpose(const float* __restrict__ conf)
{
    __shared__ float s[TP * NCLS];          // 2688 floats
    const int bb   = blockIdx.x / NTILE;
    const int tile = blockIdx.x % NTILE;
    const int p0 = tile * TP;
    const int tid = threadIdx.x;
    const int nval = min(TP, NPRI - p0) * NCLS;   // multiple of 4 (NPRI%4==0)
    const float4* src4 = (const float4*)(conf + ((size_t)bb * NPRI + p0) * NCLS);
    const int nv4 = nval >> 2;
    float4* s4 = (float4*)s;
    for (int i = tid; i < nv4; i += 256) s4[i] = __ldg(src4 + i);
    __syncthreads();
    for (int i = tid; i < (TP / 4) * NCLS; i += 256) {
        int c = i >> 5;                     // 0..20
        int g = i & 31;                     // prior group of 4
        int p = p0 + g * 4;
        if (p < NPRI) {                     // groups are whole (NPRI%4==0)
            float4 v;
            v.x = s[(g * 4 + 0) * NCLS + c];
            v.y = s[(g * 4 + 1) * NCLS + c];
            v.z = s[(g * 4 + 2) * NCLS + c];
            v.w = s[(g * 4 + 3) * NCLS + c];
            *(float4*)&g_confT[bb * NCLS + c][p] = v;
        }
    }
}

// ============ K1: detect (R10 pipeline; bitonic replaced by exact histogram sort) ============
__global__ void __launch_bounds__(NTHREADS)
detect_kernel(const float* __restrict__ loc, float* __restrict__ out)
{
    extern __shared__ unsigned char raw[];
    Smem& S = *reinterpret_cast<Smem*>(raw);

    const int lane_id = blockIdx.x;
    const int b = lane_id / NCLS, c = lane_id % NCLS;
    float* outp = out + (size_t)lane_id * TOPK * 5;
    const int tid = threadIdx.x, lane = tid & 31, warp = tid >> 5;
    const unsigned lanem_lt = (1u << lane) - 1u;

    if (c == 0) {
        for (int i = tid; i < TOPK * 5; i += NTHREADS) outp[i] = 0.0f;
        return;
    }
    if (tid == 0) { S.count = 0; S.fp = 0x7FFFFFFF; }
    __syncthreads();

    // ---- Phase A: collect passers (coalesced, 9-deep preload x2, warp-aggregated) ----
    const float* confc = g_confT[lane_id];
    #pragma unroll
    for (int half = 0; half < 2; ++half) {
        float sv[9];
        #pragma unroll
        for (int t = 0; t < 9; ++t) {
            int p = tid + (half * 9 + t) * NTHREADS;
            sv[t] = (p < NPRI) ? confc[p] : 0.0f;
        }
        #pragma unroll
        for (int t = 0; t < 9; ++t) {
            int p = tid + (half * 9 + t) * NTHREADS;
            bool pass = sv[t] > CONF_TH;
            unsigned m = __ballot_sync(0xFFFFFFFFu, pass);
            if (m) {
                int leader = __ffs(m) - 1, bp = 0;
                if (lane == leader) {
                    bp = atomicAdd(&S.count, __popc(m));
                    atomicMin(&S.fp, p);
                }
                bp = __shfl_sync(0xFFFFFFFFu, bp, leader);
                if (pass) {
                    int pos = bp + __popc(m & lanem_lt);
                    if (pos < CAP)
                        S.key[pos] = ((unsigned long long)__float_as_uint(sv[t]) << 32)
                                   | (unsigned)(0xFFFFFFFFu - (unsigned)p);
                }
            }
        }
    }
    __syncthreads();
    const int count = min(S.count, CAP);
    if (count == 0) {
        for (int i = tid; i < TOPK * 5; i += NTHREADS) outp[i] = 0.0f;
        return;
    }

    // ---- Phase B: EXACT descending sort via monotone bucket histogram ----
    // bucket(s) = clamp((s_bits - bits(0.95f)) >> 9) is monotone in score;
    // ties within a bucket resolved by full u64 comparison -> exact total order.
    {
        unsigned* hist = (unsigned*)S.wmask;           // [0,1664)
        unsigned* hoff = (unsigned*)S.wmask + 2048;    // [2048,3712)
        unsigned* arr  = (unsigned*)S.wmask + 4096;    // [4096,5760)
        unsigned long long* scat = (unsigned long long*)S.wbox;  // 1200 u64 >= CAP

        for (int i = tid; i < NBUCK; i += NTHREADS) { hist[i] = 0; arr[i] = 0; }
        __syncthreads();
        for (int t = tid; t < count; t += NTHREADS) {
            unsigned sb = (unsigned)(S.key[t] >> 32);
            unsigned bk = min(1663u, (sb - 0x3F733333u) >> 9);
            atomicAdd(&hist[bk], 1u);
        }
        __syncthreads();
        // exclusive suffix-sum: hoff[b] = # keys in buckets > b
        {
            int t4 = tid * 4;
            unsigned v[4];
            #pragma unroll
            for (int k = 0; k < 4; ++k) {
                int rb = NBUCK - 1 - (t4 + k);
                v[k] = (rb >= 0) ? hist[rb] : 0u;
            }
            unsigned ts = v[0] + v[1] + v[2] + v[3];
            unsigned inc = ts;
            #pragma unroll
            for (int d = 1; d < 32; d <<= 1) {
                unsigned u = __shfl_up_sync(0xFFFFFFFFu, inc, d);
                if (lane >= d) inc += u;
            }
            if (lane == 31) S.wscan[warp] = inc;
            __syncthreads();
            if (warp == 0) {
                unsigned w = (lane < NWARPS) ? S.wscan[lane] : 0u;
                unsigned wi = w;
                #pragma unroll
                for (int d = 1; d < 32; d <<= 1) {
                    unsigned u = __shfl_up_sync(0xFFFFFFFFu, wi, d);
                    if (lane >= d) wi += u;
                }
                if (lane < NWARPS) S.wscan[lane] = wi - w;   // exclusive warp base
            }
            __syncthreads();
            unsigned e = S.wscan[warp] + inc - ts;
            #pragma unroll
            for (int k = 0; k < 4; ++k) {
                int rb = NBUCK - 1 - (t4 + k);
                if (rb >= 0) hoff[rb] = e;
                e += v[k];
            }
        }
        __syncthreads();
        // scatter in arrival order into bucket regions
        for (int t = tid; t < count; t += NTHREADS) {
            unsigned long long kv = S.key[t];
            unsigned sb = (unsigned)(kv >> 32);
            unsigned bk = min(1663u, (sb - 0x3F733333u) >> 9);
            unsigned slot = hoff[bk] + atomicAdd(&arr[bk], 1u);
            scat[slot] = kv;
        }
        __syncthreads();
        // exact rank within (tiny) bucket -> final position
        for (int t = tid; t < count; t += NTHREADS) {
            unsigned long long kv = scat[t];
            unsigned sb = (unsigned)(kv >> 32);
            unsigned bk = min(1663u, (sb - 0x3F733333u) >> 9);
            unsigned base = hoff[bk], sz = hist[bk];
            unsigned rk = 0;
            for (unsigned i = base; i < base + sz; ++i)
                rk += (scat[i] > kv) ? 1u : 0u;
            S.key[base + rk] = kv;
        }
        __syncthreads();
    }

    // ---- Phase C: gather boxes ----
    const int M = min(count, MCAND);
    const int ngroups = (M + 31) >> 5;
    for (int t = tid; t < M; t += NTHREADS) {
        int p = (int)(0xFFFFFFFFu - (unsigned)(S.key[t] & 0xFFFFFFFFu));
        float4 L = __ldg((const float4*)(loc + ((size_t)b * NPRI + p) * 4));
        S.box[t]  = L;
        S.area[t] = (L.z - L.x) * (L.w - L.y);
    }
    __syncthreads();

    // ---- Phase C2: compaction of well-formed boxes (degenerates never interact) ----
    for (int cs = warp; cs < ngroups; cs += NWARPS) {
        int t = cs * 32 + lane;
        bool wf = false;
        if (t < M) { float4 B = S.box[t]; wf = (B.z > B.x) && (B.w > B.y); }
        unsigned m = __ballot_sync(0xFFFFFFFFu, wf);
        if (lane == 0) { S.wfball[cs] = m; S.wfoff[cs] = __popc(m); }
    }
    __syncthreads();
    if (tid == 0) {
        int run = 0;
        for (int cs = 0; cs < ngroups; ++cs) { int cc = S.wfoff[cs]; S.wfoff[cs] = run; run += cc; }
        S.nwf = run;
    }
    __syncthreads();
    const int nwf = S.nwf;
    for (int cs = warp; cs < ngroups; cs += NWARPS) {
        int t = cs * 32 + lane;
        if (t < M) {
            unsigned m = S.wfball[cs];
            bool wf = (m >> lane) & 1u;
            int pos = S.wfoff[cs] + __popc(m & lanem_lt);
            S.cidx[t] = wf ? (short)pos : (short)-1;
            if (wf) { S.wbox[pos] = S.box[t]; S.warea[pos] = S.area[t]; }
        }
    }
    __syncthreads();

    const int ngw = (nwf + 31) >> 5;

    // ---- Phase D: IoU mask on compact set ----
    {
        int tcnt = 0;
        for (int w = 0; w < ngw; ++w) {
            const int j0 = w * 32;
            const int jmax = min(32, nwf - j0);
            for (int g = 0; g <= w; ++g, ++tcnt) {
                if ((tcnt & (NWARPS - 1)) != warp) continue;
                const int i = g * 32 + lane;
                const bool rv = i < nwf;
                float4 bi = rv ? S.wbox[i] : make_float4(0, 0, 0, 0);
                float  ai = rv ? S.warea[i] : 0.0f;
                unsigned bits = 0, uncb = 0;
                #pragma unroll 8
                for (int t2 = 0; t2 < jmax; ++t2) {
                    float4 bj = S.wbox[j0 + t2];
                    float  aj = S.warea[j0 + t2];
                    float inter = fmaxf(fminf(bi.z, bj.z) - fmaxf(bi.x, bj.x), 0.0f)
                                * fmaxf(fminf(bi.w, bj.w) - fmaxf(bi.y, bj.y), 0.0f);
                    float un = ai + aj - inter;
                    float d  = fmaf(-NMS_TH, un, inter);
                    float mg = 2e-6f * (fabsf(inter) + fabsf(un));
                    bool sup = (un > 0.0f) ? (d > mg) : (d < -mg);
                    bool unc = !(fabsf(d) > mg) || (un == 0.0f);
                    if (sup) bits |= 1u << t2;
                    if (unc) uncb |= 1u << t2;
                }
                if (uncb) {
                    do {
                        int t2 = __ffs(uncb) - 1; uncb &= uncb - 1;
                        float4 bj = S.wbox[j0 + t2];
                        float  aj = S.warea[j0 + t2];
                        float inter = fmaxf(fminf(bi.z, bj.z) - fmaxf(bi.x, bj.x), 0.0f)
                                    * fmaxf(fminf(bi.w, bj.w) - fmaxf(bi.y, bj.y), 0.0f);
                        float un = ai + aj - inter;
                        if (__fdiv_rn(inter, un) > NMS_TH) bits |= 1u << t2;
                        else bits &= ~(1u << t2);
                    } while (uncb);
                }
                if (g == w) bits &= (0xFFFFFFFEu << lane);
                if (rv) S.wmask[w * MPITCH + i] = bits;
            }
        }
    }
    __syncthreads();

    // ---- Phase E: compact greedy sweep (warp 0) ----
    if (warp == 0 && nwf > 0) {
        unsigned acc = 0;
        for (int w = 0; w < ngw; ++w) {
            unsigned cur = __shfl_sync(0xFFFFFFFFu, acc, w);
            unsigned chunkkeep = 0;
            for (int sub = 0; sub < 4; ++sub) {
                const int ibase = w * 32 + sub * 8;
                if (ibase >= nwf) break;
                const int nv = min(8, nwf - ibase);
                const unsigned validm = (nv == 8) ? 0xFFu : ((1u << nv) - 1u);
                unsigned selfm[8], rowm[8], selfor = 0;
                #pragma unroll
                for (int t = 0; t < 8; ++t) {
                    bool vld = t < nv;
                    int i = ibase + t;
                    selfm[t] = vld ? S.wmask[w * MPITCH + i] : 0u;
                    rowm[t]  = (vld && lane >= w && lane < ngw)
                             ? S.wmask[lane * MPITCH + i] : 0u;
                    selfor |= selfm[t];
                }
                unsigned keepb;
                if (selfor == 0) {
                    keepb = validm & ~((cur >> (sub * 8)) & 0xFFu);
                    #pragma unroll
                    for (int t = 0; t < 8; ++t)
                        acc |= rowm[t] & (unsigned)(-(int)((keepb >> t) & 1u));
                } else {
                    keepb = 0;
                    #pragma unroll
                    for (int t = 0; t < 8; ++t) {
                        int kbit = sub * 8 + t;
                        if (((validm >> t) & 1u) && !((cur >> kbit) & 1u)) {
                            keepb |= 1u << t;
                            cur |= selfm[t];
                            acc |= rowm[t];
                        }
                    }
                }
                chunkkeep |= keepb << (sub * 8);
            }
            if (lane == 0) S.kwbits[w] = chunkkeep;
        }
    }
    __syncthreads();

    // ---- Phase F: flag scan + scatter output ----
    for (int cs = warp; cs < ngroups; cs += NWARPS) {
        int t = cs * 32 + lane;
        bool flag = false;
        if (t < M) {
            int ci = S.cidx[t];
            flag = (ci < 0) ? true : (((S.kwbits[ci >> 5] >> (ci & 31)) & 1u) != 0);
        }
        unsigned fb = __ballot_sync(0xFFFFFFFFu, flag);
        if (lane == 0) { S.flagb[cs] = fb; S.ctoff[cs] = __popc(fb); }
    }
    __syncthreads();
    if (tid == 0) {
        int run = 0;
        for (int cs = 0; cs < ngroups; ++cs) { int cc = S.ctoff[cs]; S.ctoff[cs] = run; run += cc; }
        S.ntot = run;
    }
    __syncthreads();
    const int n = min(S.ntot, TOPK);
    const int fp = S.fp;

    for (int cs = warp; cs < ngroups; cs += NWARPS) {
        int t = cs * 32 + lane;
        unsigned fb = S.flagb[cs];
        bool flag = ((fb >> lane) & 1u) && (t < M);
        int rank = S.ctoff[cs] + __popc(fb & lanem_lt);
        if (flag && rank < TOPK) {
            float sc = __uint_as_float((unsigned)(S.key[t] >> 32));
            float4 bb = S.box[t];
            float* o = outp + rank * 5;
            o[0] = sc; o[1] = bb.x; o[2] = bb.y; o[3] = bb.z; o[4] = bb.w;
        }
    }
    {
        float4 fb4 = __ldg((const float4*)(loc + ((size_t)b * NPRI + fp) * 4));
        for (int r = n + tid; r < TOPK; r += NTHREADS) {
            float* o = outp + r * 5;
            o[0] = 0.0f; o[1] = fb4.x; o[2] = fb4.y; o[3] = fb4.z; o[4] = fb4.w;
        }
    }
}

extern "C" void kernel_launch(void* const* d_in, const int* in_sizes, int n_in,
                              void* d_out, int out_size)
{
    const float* loc  = (const float*)d_in[0];   // [8, 8732, 4]
    const float* conf = (const float*)d_in[1];   // [8, 8732, 21]
    float* out = (float*)d_out;                  // [8, 21, 200, 5]

    static int configured = 0;
    if (!configured) {
        cudaFuncSetAttribute(detect_kernel,
                             cudaFuncAttributeMaxDynamicSharedMemorySize,
                             (int)sizeof(Smem));
        configured = 1;
    }
    k0_transpose<<<NBATCH * NTILE, 256>>>(conf);
    detect_kernel<<<NLANES, NTHREADS, sizeof(Smem)>>>(loc, out);
}